// round 5
// baseline (speedup 1.0000x reference)
#include <cuda_runtime.h>
#include <math.h>

#define Ldim 4
#define Bdim 128
#define INd  512
#define CTXd 512
#define STd  512
#define Rd   256
#define Cd   256
#define Dd   1536   // IN + CTX + ST

typedef unsigned long long u64;

// packed f32x2 helpers (Blackwell sm_103a; ptxas never emits FFMA2 from C++)
__device__ __forceinline__ u64 pack_rep(float a) {
    u64 r;
    asm("mov.b64 %0, {%1, %1};" : "=l"(r) : "f"(a));
    return r;
}
__device__ __forceinline__ void fma2(u64& acc, u64 a, u64 b) {
    asm("fma.rn.f32x2 %0, %1, %2, %0;" : "+l"(acc) : "l"(a), "l"(b));
}
__device__ __forceinline__ void unpack2(float& lo, float& hi, u64 v) {
    asm("mov.b64 {%0, %1}, %2;" : "=f"(lo), "=f"(hi) : "l"(v));
}

// ---------------- scratch (device globals; no allocation) ----------------
__device__ float g_u  [Ldim*Bdim*Rd];
__device__ float g_v  [Ldim*Bdim*Cd];
__device__ float g_ge [2*Ldim];           // sigmoid(gamma), sigmoid(eta)

// ================= fused gate GEMM + h_new epilogue =================
// A = [x | c | h[l]] read SEGMENTED directly (no concat).
// phi/alpha/beta share the A tile; h_new = sig(alpha)*tanh(phi)+sig(beta)*h.
// Tiles: 64(b) x 16(o), K-tile 32, 128 threads, thread tile 4x2 per head,
// accumulators packed f32x2 along the o-pair. Grid = 256 blocks.
#define GBB 64
#define GBO 16
#define GBK 32

__global__ __launch_bounds__(128) void gate_fused_kernel(
        const float* __restrict__ x,      const float* __restrict__ c,
        const float* __restrict__ h,
        const float* __restrict__ phi_w,  const float* __restrict__ alpha_w,
        const float* __restrict__ beta_w, const float* __restrict__ phi_b,
        const float* __restrict__ alpha_b,const float* __restrict__ beta_b,
        float* __restrict__ hnew) {
    __shared__ __align__(16) float As[GBK][GBB + 4];      // stride 68 floats (272B)
    __shared__ __align__(16) float Ws[3][GBK][GBO + 4];   // stride 20 floats (80B, 8B-mult)

    const int zt = blockIdx.y;
    const int l  = zt >> 1;
    const int bt = zt & 1;
    const int o_base = blockIdx.x * GBO;
    const int b_base = bt * GBB;

    const float* Wm[3] = {phi_w, alpha_w, beta_w};

    const int tid = threadIdx.x;       // 128
    const int tx = tid & 7;            // o-group 0..7 (x2 -> 16 o)
    const int ty = tid >> 3;           // b-group 0..15 (x4 -> 64 b)

    u64 acc2[3][4];                    // [head][i], lanes = (o_j0, o_j1)
    #pragma unroll
    for (int m = 0; m < 3; m++)
        #pragma unroll
        for (int i = 0; i < 4; i++) acc2[m][i] = 0ull;

    for (int k0 = 0; k0 < Dd; k0 += GBK) {
        // segment select (uniform across block)
        const float* Asrc; int Astride; int koff;
        if (k0 < INd)             { Asrc = x; Astride = INd;  koff = k0; }
        else if (k0 < INd + CTXd) { Asrc = c; Astride = CTXd; koff = k0 - INd; }
        else { Asrc = h + (size_t)l*Bdim*STd; Astride = STd; koff = k0 - INd - CTXd; }

        // A tile: 64 rows x 32 k = 512 float4, 4 per thread (transpose to [k][b])
        #pragma unroll
        for (int j = 0; j < 4; j++) {
            int g  = tid + j * 128;
            int bb = g >> 3;
            int kk = (g & 7) << 2;
            float4 v = *(const float4*)(Asrc + (size_t)(b_base + bb)*Astride + koff + kk);
            As[kk+0][bb] = v.x; As[kk+1][bb] = v.y;
            As[kk+2][bb] = v.z; As[kk+3][bb] = v.w;
        }
        // W tiles (3 heads): 16 rows x 32 k = 128 float4, 1 per thread
        #pragma unroll
        for (int m = 0; m < 3; m++) {
            const float* Wblk = Wm[m] + ((size_t)l*STd + o_base) * Dd;
            int oo = tid >> 3;             // 0..15
            int kk = (tid & 7) << 2;
            float4 v = *(const float4*)(Wblk + (size_t)oo*Dd + k0 + kk);
            Ws[m][kk+0][oo] = v.x; Ws[m][kk+1][oo] = v.y;
            Ws[m][kk+2][oo] = v.z; Ws[m][kk+3][oo] = v.w;
        }
        __syncthreads();

        #pragma unroll
        for (int kk = 0; kk < GBK; kk++) {
            float4 a = *(const float4*)(&As[kk][ty*4]);
            u64 arep[4] = {pack_rep(a.x), pack_rep(a.y), pack_rep(a.z), pack_rep(a.w)};
            #pragma unroll
            for (int m = 0; m < 3; m++) {
                u64 w64 = *(const u64*)(&Ws[m][kk][tx*2]);   // LDS.64, 8B-aligned
                #pragma unroll
                for (int i = 0; i < 4; i++)
                    fma2(acc2[m][i], arep[i], w64);
            }
        }
        __syncthreads();
    }

    // epilogue: biases, activations
    const int oo = o_base + tx*2;
    float2 pb = *(const float2*)(phi_b   + (size_t)l*STd + oo);
    float2 ab = *(const float2*)(alpha_b + (size_t)l*STd + oo);
    float2 bb = *(const float2*)(beta_b  + (size_t)l*STd + oo);
    float pbv[2] = {pb.x, pb.y};
    float abv[2] = {ab.x, ab.y};
    float bbv[2] = {bb.x, bb.y};

    #pragma unroll
    for (int i = 0; i < 4; i++) {
        int b = b_base + ty*4 + i;
        float2 hv = *(const float2*)(h + ((size_t)l*Bdim + b)*STd + oo);
        float hvv[2] = {hv.x, hv.y};
        float pacc[2], aacc[2], bacc[2];
        unpack2(pacc[0], pacc[1], acc2[0][i]);
        unpack2(aacc[0], aacc[1], acc2[1][i]);
        unpack2(bacc[0], bacc[1], acc2[2][i]);
        float2 o;
        float* op = &o.x;
        #pragma unroll
        for (int j = 0; j < 2; j++) {
            float phi = pacc[j] + pbv[j];
            float al  = 1.0f / (1.0f + expf(-(aacc[j] + abv[j])));
            float be  = 1.0f / (1.0f + expf(-(bacc[j] + bbv[j])));
            op[j] = al * tanhf(phi) + be * hvv[j];
        }
        *(float2*)(hnew + ((size_t)l*Bdim + b)*STd + oo) = o;
    }
}

// ================= u/v GEMM =================
// A = [h_new | x | c] read SEGMENTED (h_new straight from d_out).
// Tiles: 32(b) x 32(o), K-tile 32, 128 threads, thread tile 2x4 (f32x2 on o-pairs).
// Grid = 8 o-tiles * 2 heads * 16 (l,bt) = 256 blocks.
#define UBB 32
#define UBO 32
#define UBK 32

__global__ __launch_bounds__(128) void uv_gemm_kernel(
        const float* __restrict__ hnew, const float* __restrict__ x,
        const float* __restrict__ c,
        const float* __restrict__ W0, const float* __restrict__ W1,
        const float* __restrict__ b0, const float* __restrict__ b1) {
    __shared__ __align__(16) float As[UBK][UBB + 4];   // stride 36 floats (144B, 8B-mult)
    __shared__ __align__(16) float Ws[UBK][UBO + 4];

    const int m  = blockIdx.y;              // 0: u, 1: v
    const int zt = blockIdx.z;              // 0..15
    const int l  = zt >> 2;
    const int bt = zt & 3;

    const float* W    = (m == 0) ? W0 : W1;
    const float* bias = (m == 0) ? b0 : b1;
    float* out        = (m == 0) ? g_u : g_v;
    const int O = Rd;                       // Rd == Cd == 256

    const int o_base = blockIdx.x * UBO;
    const int b_base = bt * UBB;

    const float* Wblk = W + ((size_t)l*O + o_base) * Dd;

    const int tid = threadIdx.x;
    const int tx = tid & 7;                 // x4 -> 32 o
    const int ty = tid >> 3;                // x2 -> 32 b

    u64 acc2[2][2] = {{0ull,0ull},{0ull,0ull}};   // [i][o-pair]

    for (int k0 = 0; k0 < Dd; k0 += UBK) {
        const float* Asrc; int Astride; int koff;
        if (k0 < STd)            { Asrc = hnew + (size_t)l*Bdim*STd; Astride = STd; koff = k0; }
        else if (k0 < STd + INd) { Asrc = x; Astride = INd;  koff = k0 - STd; }
        else                     { Asrc = c; Astride = CTXd; koff = k0 - STd - INd; }

        // A tile: 32 rows x 32 k = 256 float4, 2 per thread
        #pragma unroll
        for (int j = 0; j < 2; j++) {
            int g  = tid + j * 128;
            int bb = g >> 3;
            int kk = (g & 7) << 2;
            float4 v = *(const float4*)(Asrc + (size_t)(b_base + bb)*Astride + koff + kk);
            As[kk+0][bb] = v.x; As[kk+1][bb] = v.y;
            As[kk+2][bb] = v.z; As[kk+3][bb] = v.w;
        }
        // W tile: 32 rows x 32 k = 256 float4, 2 per thread
        #pragma unroll
        for (int j = 0; j < 2; j++) {
            int g  = tid + j * 128;
            int oo = g >> 3;
            int kk = (g & 7) << 2;
            float4 v = *(const float4*)(Wblk + (size_t)oo*Dd + k0 + kk);
            Ws[kk+0][oo] = v.x; Ws[kk+1][oo] = v.y;
            Ws[kk+2][oo] = v.z; Ws[kk+3][oo] = v.w;
        }
        __syncthreads();

        #pragma unroll
        for (int kk = 0; kk < UBK; kk++) {
            float2 a = *(const float2*)(&As[kk][ty*2]);
            u64 ar0 = pack_rep(a.x);
            u64 ar1 = pack_rep(a.y);
            u64 w0 = *(const u64*)(&Ws[kk][tx*4]);       // o j0,j1
            u64 w1 = *(const u64*)(&Ws[kk][tx*4 + 2]);   // o j2,j3
            fma2(acc2[0][0], ar0, w0);
            fma2(acc2[0][1], ar0, w1);
            fma2(acc2[1][0], ar1, w0);
            fma2(acc2[1][1], ar1, w1);
        }
        __syncthreads();
    }

    const int oo = o_base + tx*4;
    float4 bb4 = *(const float4*)(bias + (size_t)l*O + oo);
    float bv[4] = {bb4.x, bb4.y, bb4.z, bb4.w};
    #pragma unroll
    for (int i = 0; i < 2; i++) {
        int b = b_base + ty*2 + i;
        float r0, r1, r2, r3;
        unpack2(r0, r1, acc2[i][0]);
        unpack2(r2, r3, acc2[i][1]);
        float4 o;
        o.x = r0 + bv[0];
        o.y = r1 + bv[1];
        o.z = r2 + bv[2];
        o.w = r3 + bv[3];
        *(float4*)(out + ((size_t)l*Bdim + b)*O + oo) = o;
    }
}

// ---------------- precompute sigmoid(gamma), sigmoid(eta) ----------------
__global__ void sig_kernel(const float* __restrict__ gamma, const float* __restrict__ eta) {
    int i = threadIdx.x;
    if (i < Ldim)          g_ge[i] = 1.0f / (1.0f + expf(-gamma[i]));
    else if (i < 2*Ldim)   g_ge[i] = 1.0f / (1.0f + expf(-eta[i - Ldim]));
}

// ---------------- M update: all 4 levels per thread (neighbor reuse in registers) ----
__global__ void mupdate_kernel(const float* __restrict__ M, float* __restrict__ Mout) {
    int idx = blockIdx.x * blockDim.x + threadIdx.x;   // B*R*C/4
    int c4 = idx & 63;            // C/4 = 64
    int r  = (idx >> 6) & 255;
    int b  = idx >> 14;
    size_t base = ((size_t)b*Rd + r)*Cd + (size_t)c4*4;
    const size_t LS = (size_t)Bdim*Rd*Cd;

    float4 m[Ldim];
    #pragma unroll
    for (int l = 0; l < Ldim; l++) m[l] = *(const float4*)(M + l*LS + base);

    float uu[Ldim];
    float4 vv[Ldim];
    #pragma unroll
    for (int l = 0; l < Ldim; l++) {
        uu[l] = g_u[((size_t)l*Bdim + b)*Rd + r];
        vv[l] = *(const float4*)(g_v + ((size_t)l*Bdim + b)*Cd + (size_t)c4*4);
    }

    #pragma unroll
    for (int l = 0; l < Ldim; l++) {
        int lu = (l == 0) ? 0 : l - 1;
        int ld = (l == Ldim-1) ? Ldim-1 : l + 1;
        float g = g_ge[l];
        float e = g_ge[Ldim + l];
        float omg = 1.0f - g;
        float hg  = 0.5f * g;
        float eu  = e * uu[l];
        float4 o;
        o.x = omg*m[l].x + hg*(m[lu].x + m[ld].x) + eu*vv[l].x;
        o.y = omg*m[l].y + hg*(m[lu].y + m[ld].y) + eu*vv[l].y;
        o.z = omg*m[l].z + hg*(m[lu].z + m[ld].z) + eu*vv[l].z;
        o.w = omg*m[l].w + hg*(m[lu].w + m[ld].w) + eu*vv[l].w;
        *(float4*)(Mout + l*LS + base) = o;
    }
}

// ---------------- launch ----------------
extern "C" void kernel_launch(void* const* d_in, const int* in_sizes, int n_in,
                              void* d_out, int out_size) {
    const float* x       = (const float*)d_in[0];
    const float* c       = (const float*)d_in[1];
    const float* h       = (const float*)d_in[2];
    const float* M       = (const float*)d_in[3];
    const float* phi_w   = (const float*)d_in[4];
    const float* phi_b   = (const float*)d_in[5];
    const float* alpha_w = (const float*)d_in[6];
    const float* alpha_b = (const float*)d_in[7];
    const float* beta_w  = (const float*)d_in[8];
    const float* beta_b  = (const float*)d_in[9];
    const float* u_w     = (const float*)d_in[10];
    const float* u_b     = (const float*)d_in[11];
    const float* v_w     = (const float*)d_in[12];
    const float* v_b     = (const float*)d_in[13];
    const float* gamma   = (const float*)d_in[14];
    const float* eta     = (const float*)d_in[15];

    float* out  = (float*)d_out;
    float* hnew = out;                               // (L,B,ST)
    float* Mout = out + (size_t)Ldim*Bdim*STd;       // (L,B,R,C)

    // tiny, off-critical-path
    sig_kernel<<<1, 32>>>(gamma, eta);

    // fused phi/alpha/beta GEMM + h_new epilogue (reads x/c/h directly)
    gate_fused_kernel<<<dim3(STd/GBO, Ldim*2), 128>>>(
        x, c, h, phi_w, alpha_w, beta_w, phi_b, alpha_b, beta_b, hnew);

    // u, v (reads [h_new|x|c] directly, h_new from d_out)
    uv_gemm_kernel<<<dim3(Rd/UBO, 2, 4*Ldim), 128>>>(
        hnew, x, c, u_w, v_w, u_b, v_b);

    // M_new
    mupdate_kernel<<<(Bdim*Rd*Cd/4)/256, 256>>>(M, Mout);
}